// round 5
// baseline (speedup 1.0000x reference)
#include <cuda_runtime.h>

#define BB 128
#define NN 512
#define DD 300
#define AA 32

typedef unsigned long long ull;

// packed f32x2 helpers (sm_103a)
__device__ __forceinline__ void fma2(ull& d, ull a, ull b) {
    asm("fma.rn.f32x2 %0, %1, %2, %0;" : "+l"(d) : "l"(a), "l"(b));
}
__device__ __forceinline__ ull mul2(ull a, ull b) {
    ull r; asm("mul.rn.f32x2 %0, %1, %2;" : "=l"(r) : "l"(a), "l"(b)); return r;
}
__device__ __forceinline__ ull dup2(float x) {
    ull r; asm("mov.b64 %0, {%1, %1};" : "=l"(r) : "f"(x)); return r;
}
__device__ __forceinline__ void unpack2(ull v, float& lo, float& hi) {
    asm("mov.b64 {%0, %1}, %2;" : "=f"(lo), "=f"(hi) : "l"(v));
}
__device__ __forceinline__ ull pack2(float lo, float hi) {
    ull r; asm("mov.b64 %0, {%1, %2};" : "=l"(r) : "f"(lo), "f"(hi)); return r;
}

// Scratch: Q row-major [B*N, A]; K transposed per batch [B][A][N]
__device__ float g_Q[BB * NN * AA];
__device__ float g_Kt[BB * AA * NN];

// ---------------------------------------------------------------------------
// Kernel 1: Q|K projection. GEMM [65536, 300] @ [300, 64].
// ---------------------------------------------------------------------------
__global__ __launch_bounds__(256) void qk_kernel(
    const float* __restrict__ X,
    const float* __restrict__ Wq,
    const float* __restrict__ Wk)
{
    __shared__ float Xs[256 * 9];
    __shared__ float Ws[8 * 68];

    const int tid = threadIdx.x;
    const int row0 = blockIdx.x * 256;
    const int rg = tid >> 3;
    const int cg = tid & 7;

    ull acc[8][4];
#pragma unroll
    for (int i = 0; i < 8; i++)
#pragma unroll
        for (int j = 0; j < 4; j++) acc[i][j] = 0ull;

    float xf[8];
    float wf[2];
    const float* xrow = X + (long)(row0 + tid) * DD;
    const int wk0 = tid >> 6,  wa0 = tid & 63;
    const int wk1 = (tid + 256) >> 6, wa1 = (tid + 256) & 63;

    auto prefetch = [&](int k0) {
        if (k0 + 8 <= DD) {
            float4 v0 = *(const float4*)(xrow + k0);
            float4 v1 = *(const float4*)(xrow + k0 + 4);
            xf[0] = v0.x; xf[1] = v0.y; xf[2] = v0.z; xf[3] = v0.w;
            xf[4] = v1.x; xf[5] = v1.y; xf[6] = v1.z; xf[7] = v1.w;
        } else {
#pragma unroll
            for (int kk = 0; kk < 8; kk++)
                xf[kk] = (k0 + kk < DD) ? xrow[k0 + kk] : 0.0f;
        }
        wf[0] = (k0 + wk0 < DD)
              ? ((wa0 < 32) ? Wq[(k0 + wk0) * AA + wa0] : Wk[(k0 + wk0) * AA + wa0 - 32])
              : 0.0f;
        wf[1] = (k0 + wk1 < DD)
              ? ((wa1 < 32) ? Wq[(k0 + wk1) * AA + wa1] : Wk[(k0 + wk1) * AA + wa1 - 32])
              : 0.0f;
    };

    prefetch(0);

    for (int k0 = 0; k0 < DD; k0 += 8) {
        {
            float* xs = &Xs[tid * 9];
#pragma unroll
            for (int kk = 0; kk < 8; kk++) xs[kk] = xf[kk];
            Ws[wk0 * 68 + wa0] = wf[0];
            Ws[wk1 * 68 + wa1] = wf[1];
        }
        __syncthreads();
        if (k0 + 8 < DD) prefetch(k0 + 8);

#pragma unroll
        for (int k = 0; k < 8; k++) {
            ull ad[8];
#pragma unroll
            for (int i = 0; i < 8; i++) ad[i] = dup2(Xs[(rg * 8 + i) * 9 + k]);
            ull bv[4];
#pragma unroll
            for (int j = 0; j < 4; j++)
                bv[j] = *(const ull*)&Ws[k * 68 + cg * 8 + 2 * j];
#pragma unroll
            for (int i = 0; i < 8; i++)
#pragma unroll
                for (int j = 0; j < 4; j++) fma2(acc[i][j], bv[j], ad[i]);
        }
        __syncthreads();
    }

#pragma unroll
    for (int i = 0; i < 8; i++) {
        const int row = row0 + rg * 8 + i;
        const int b = row >> 9;
        const int n = row & 511;
#pragma unroll
        for (int j = 0; j < 4; j++) {
            const int c = cg * 8 + 2 * j;
            float lo, hi; unpack2(acc[i][j], lo, hi);
            if (c < 32) {
                *(ull*)&g_Q[row * AA + c] = acc[i][j];
            } else {
                g_Kt[b * (AA * NN) + (c - 32) * NN + n] = lo;
                g_Kt[b * (AA * NN) + (c - 31) * NN + n] = hi;
            }
        }
    }
}

// ---------------------------------------------------------------------------
// Kernel 2: fused scores + adj + softmax (in registers) + attn@X. 512 thr.
// smem: Ps[64][512] | KXs (Kst[32][512] then Xs[32][304]) | Qs[64][32]
// ---------------------------------------------------------------------------
#define SM_PS   0
#define SM_KX   (64 * 512)
#define SM_QS   (64 * 512 + 32 * 512)
#define SM_WORDS (64 * 512 + 32 * 512 + 64 * 32)

__global__ __launch_bounds__(512, 1) void attn_kernel(
    const float* __restrict__ X,
    const float* __restrict__ adj,
    float* __restrict__ out)
{
    extern __shared__ float sm[];
    float* Ps  = sm + SM_PS;
    float* KXs = sm + SM_KX;
    float* Qs  = sm + SM_QS;

    const int tid = threadIdx.x;
    const int b = blockIdx.x >> 3;
    const int row0 = (blockIdx.x & 7) * 64;

    // ---- stage Kst[k][m] and Qs ----
    {
        const float4* gk4 = (const float4*)(g_Kt + b * (AA * NN));
        float4* ks4 = (float4*)KXs;
        for (int idx = tid; idx < (AA * NN) / 4; idx += 512)
            ks4[idx] = gk4[idx];
        const float4* gq4 = (const float4*)(g_Q + (b * NN + row0) * AA);
        float4* qs4 = (float4*)Qs;
        for (int idx = tid; idx < (64 * AA) / 4; idx += 512)
            qs4[idx] = gq4[idx];
    }
    __syncthreads();

    // ---- Phase 1: scores = (Q K^T) * adj, then softmax entirely in
    //      registers (each warp owns 4 full rows), single write of P ----
    {
        const int tx = tid & 31;       // m-pair lane
        const int ty = tid >> 5;       // warp: rows ty*4..ty*4+3
        const int rl0 = ty * 4;
        ull acc[4][8];
#pragma unroll
        for (int i = 0; i < 4; i++)
#pragma unroll
            for (int jm = 0; jm < 8; jm++) acc[i][jm] = 0ull;

        for (int k = 0; k < AA; k++) {
            ull qd[4];
#pragma unroll
            for (int i = 0; i < 4; i++) qd[i] = dup2(Qs[(rl0 + i) * AA + k]);
            const float* Krow = &KXs[k * NN + 2 * tx];
#pragma unroll
            for (int jm = 0; jm < 8; jm++) {
                ull kv = *(const ull*)(Krow + 64 * jm);
#pragma unroll
                for (int i = 0; i < 4; i++) fma2(acc[i][jm], kv, qd[i]);
            }
        }

#pragma unroll
        for (int i = 0; i < 4; i++) {
            const int rglob = b * NN + row0 + rl0 + i;
            const ull* arow = (const ull*)(adj + (long)rglob * NN) + tx;
            float v[16];
#pragma unroll
            for (int jm = 0; jm < 8; jm++) {
                ull prod = mul2(acc[i][jm], arow[32 * jm]);
                unpack2(prod, v[2 * jm], v[2 * jm + 1]);
            }
            float mx = -1e30f;
#pragma unroll
            for (int j = 0; j < 16; j++) mx = fmaxf(mx, v[j]);
#pragma unroll
            for (int o = 16; o > 0; o >>= 1)
                mx = fmaxf(mx, __shfl_xor_sync(0xffffffffu, mx, o));
            float s = 0.0f;
#pragma unroll
            for (int j = 0; j < 16; j++) {
                v[j] = __expf(v[j] - mx);
                s += v[j];
            }
#pragma unroll
            for (int o = 16; o > 0; o >>= 1)
                s += __shfl_xor_sync(0xffffffffu, s, o);
            const float inv = __frcp_rn(s);
#pragma unroll
            for (int jm = 0; jm < 8; jm++) {
                *(ull*)&Ps[(rl0 + i) * NN + 2 * tx + 64 * jm] =
                    pack2(v[2 * jm] * inv, v[2 * jm + 1] * inv);
            }
        }
    }
    __syncthreads();

    // ---- Phase 3: out[64,300] = P[64,512] @ X[b][512,300].
    //      16 warps = 8 row-groups (8 rows) x 2 column-sets.
    //      cset0: col-pairs lane+32j, j<3 (96 pairs); cset1: 96+lane+32j, j<2.
    //      P loaded as broadcast LDS.64 covering 2 mm-steps. ----
    {
        const int lane = tid & 31;
        const int w = tid >> 5;
        const int rg8 = w & 7;         // rows rg8*8 .. +7
        const int cset = w >> 3;       // 0 or 1
        float* Xs = KXs;               // reuse: 32 rows, stride 304

        int prow[5], pcol[5]; bool pval[5];
#pragma unroll
        for (int t = 0; t < 5; t++) {
            int idx = tid + t * 512;
            pval[t] = idx < 32 * 75;
            prow[t] = idx / 75;
            pcol[t] = idx % 75;
        }

        ull acc[8][3];
#pragma unroll
        for (int i = 0; i < 8; i++)
#pragma unroll
            for (int j = 0; j < 3; j++) acc[i][j] = 0ull;

        float4 pf[5];
#pragma unroll
        for (int t = 0; t < 5; t++)
            if (pval[t])
                pf[t] = *(const float4*)(X + (long)(b * NN + prow[t]) * DD + pcol[t] * 4);

        // column byte offsets within an Xs row, per cset
        const int c0 = (cset ? (96 + lane) : lane) * 2;   // float index of pair base

        for (int mc = 0; mc < 16; mc++) {
            const int m0 = mc * 32;
            __syncthreads();
#pragma unroll
            for (int t = 0; t < 5; t++)
                if (pval[t]) *(float4*)(Xs + prow[t] * 304 + pcol[t] * 4) = pf[t];
            __syncthreads();
            if (mc < 15) {
                const int m1 = m0 + 32;
#pragma unroll
                for (int t = 0; t < 5; t++)
                    if (pval[t])
                        pf[t] = *(const float4*)(X + (long)(b * NN + m1 + prow[t]) * DD + pcol[t] * 4);
            }

            if (cset == 0) {
#pragma unroll 2
                for (int mm = 0; mm < 32; mm += 2) {
                    float plo[8], phi[8];
#pragma unroll
                    for (int i = 0; i < 8; i++) {
                        ull pp = *(const ull*)&Ps[(rg8 * 8 + i) * NN + m0 + mm];
                        unpack2(pp, plo[i], phi[i]);
                    }
#pragma unroll
                    for (int h = 0; h < 2; h++) {
                        ull xv[3];
#pragma unroll
                        for (int j = 0; j < 3; j++)
                            xv[j] = *(const ull*)&Xs[(mm + h) * 304 + c0 + 64 * j];
#pragma unroll
                        for (int i = 0; i < 8; i++) {
                            ull pd = dup2(h ? phi[i] : plo[i]);
#pragma unroll
                            for (int j = 0; j < 3; j++) fma2(acc[i][j], xv[j], pd);
                        }
                    }
                }
            } else {
#pragma unroll 2
                for (int mm = 0; mm < 32; mm += 2) {
                    float plo[8], phi[8];
#pragma unroll
                    for (int i = 0; i < 8; i++) {
                        ull pp = *(const ull*)&Ps[(rg8 * 8 + i) * NN + m0 + mm];
                        unpack2(pp, plo[i], phi[i]);
                    }
#pragma unroll
                    for (int h = 0; h < 2; h++) {
                        ull xv[2];
#pragma unroll
                        for (int j = 0; j < 2; j++)
                            xv[j] = *(const ull*)&Xs[(mm + h) * 304 + c0 + 64 * j];
#pragma unroll
                        for (int i = 0; i < 8; i++) {
                            ull pd = dup2(h ? phi[i] : plo[i]);
#pragma unroll
                            for (int j = 0; j < 2; j++) fma2(acc[i][j], xv[j], pd);
                        }
                    }
                }
            }
        }

        const int nj = cset ? 2 : 3;
#pragma unroll
        for (int i = 0; i < 8; i++) {
            const long rglob = (long)(b * NN + row0 + rg8 * 8 + i);
            for (int j = 0; j < nj; j++) {
                const int c = c0 + 64 * j;    // float column
                if (c + 1 < DD) {
                    float lo, hi; unpack2(acc[i][j], lo, hi);
                    out[rglob * DD + c] = lo;
                    out[rglob * DD + c + 1] = hi;
                } else if (c < DD) {
                    float lo, hi; unpack2(acc[i][j], lo, hi);
                    out[rglob * DD + c] = lo;
                }
            }
        }
    }
}

// ---------------------------------------------------------------------------
extern "C" void kernel_launch(void* const* d_in, const int* in_sizes, int n_in,
                              void* d_out, int out_size)
{
    const float* X   = (const float*)d_in[0];
    const float* adj = (const float*)d_in[1];
    const float* Wq  = (const float*)d_in[2];
    const float* Wk  = (const float*)d_in[3];
    float* out = (float*)d_out;

    cudaFuncSetAttribute(attn_kernel, cudaFuncAttributeMaxDynamicSharedMemorySize,
                         SM_WORDS * sizeof(float));

    qk_kernel<<<(BB * NN) / 256, 256>>>(X, Wq, Wk);
    attn_kernel<<<BB * 8, 512, SM_WORDS * sizeof(float)>>>(X, adj, out);
}

// round 7
// speedup vs baseline: 1.0301x; 1.0301x over previous
#include <cuda_runtime.h>

#define BB 128
#define NN 512
#define DD 300
#define AA 32

typedef unsigned long long ull;
typedef unsigned int u32;

// ---------------- helpers ----------------
__device__ __forceinline__ void fma2(ull& d, ull a, ull b) {
    asm("fma.rn.f32x2 %0, %1, %2, %0;" : "+l"(d) : "l"(a), "l"(b));
}
__device__ __forceinline__ ull dup2(float x) {
    ull r; asm("mov.b64 %0, {%1, %1};" : "=l"(r) : "f"(x)); return r;
}
__device__ __forceinline__ void unpack2(ull v, float& lo, float& hi) {
    asm("mov.b64 {%0, %1}, %2;" : "=f"(lo), "=f"(hi) : "l"(v));
}
__device__ __forceinline__ u32 tf32r(float x) {
    u32 r; asm("cvt.rna.tf32.f32 %0, %1;" : "=r"(r) : "f"(x)); return r;
}
// warp-level tf32 MMA: D(16x8,f32) += A(16x8,tf32) @ B(8x8,tf32)
__device__ __forceinline__ void mma8(float4& d, const u32* a, u32 b0, u32 b1) {
    asm volatile(
        "mma.sync.aligned.m16n8k8.row.col.f32.tf32.tf32.f32 "
        "{%0,%1,%2,%3}, {%4,%5,%6,%7}, {%8,%9}, {%0,%1,%2,%3};"
        : "+f"(d.x), "+f"(d.y), "+f"(d.z), "+f"(d.w)
        : "r"(a[0]), "r"(a[1]), "r"(a[2]), "r"(a[3]), "r"(b0), "r"(b1));
}

// Scratch: Q,K row-major [B*N, A] (tf32-rounded); Xt = X^T per batch [B][304][512]
__device__ float g_Q[BB * NN * AA];
__device__ float g_K[BB * NN * AA];
__device__ float g_Xt[(long)BB * 304 * 512];   // d rows 300..303 stay zero

// ---------------------------------------------------------------------------
// Kernel 1: Q|K projection (FFMA2) + X transpose writeout, tf32-rounded outs.
// ---------------------------------------------------------------------------
__global__ __launch_bounds__(256) void qk_kernel(
    const float* __restrict__ X,
    const float* __restrict__ Wq,
    const float* __restrict__ Wk)
{
    __shared__ float Xs[256 * 9];
    __shared__ float Ws[8 * 68];

    const int tid = threadIdx.x;
    const int row0 = blockIdx.x * 256;
    const int rg = tid >> 3;
    const int cg = tid & 7;

    ull acc[8][4];
#pragma unroll
    for (int i = 0; i < 8; i++)
#pragma unroll
        for (int j = 0; j < 4; j++) acc[i][j] = 0ull;

    float xf[8], wf[2];
    const float* xrow = X + (long)(row0 + tid) * DD;
    const int wk0 = tid >> 6, wa0 = tid & 63;
    const int wk1 = (tid + 256) >> 6, wa1 = (tid + 256) & 63;

    auto prefetch = [&](int k0) {
        if (k0 + 8 <= DD) {
            float4 v0 = *(const float4*)(xrow + k0);
            float4 v1 = *(const float4*)(xrow + k0 + 4);
            xf[0] = v0.x; xf[1] = v0.y; xf[2] = v0.z; xf[3] = v0.w;
            xf[4] = v1.x; xf[5] = v1.y; xf[6] = v1.z; xf[7] = v1.w;
        } else {
#pragma unroll
            for (int kk = 0; kk < 8; kk++)
                xf[kk] = (k0 + kk < DD) ? xrow[k0 + kk] : 0.0f;
        }
        wf[0] = (k0 + wk0 < DD)
              ? ((wa0 < 32) ? Wq[(k0 + wk0) * AA + wa0] : Wk[(k0 + wk0) * AA + wa0 - 32]) : 0.0f;
        wf[1] = (k0 + wk1 < DD)
              ? ((wa1 < 32) ? Wq[(k0 + wk1) * AA + wa1] : Wk[(k0 + wk1) * AA + wa1 - 32]) : 0.0f;
    };

    prefetch(0);

    for (int k0 = 0; k0 < DD; k0 += 8) {
        {
            float* xs = &Xs[tid * 9];
#pragma unroll
            for (int kk = 0; kk < 8; kk++) xs[kk] = xf[kk];
            Ws[wk0 * 68 + wa0] = wf[0];
            Ws[wk1 * 68 + wa1] = wf[1];
        }
        __syncthreads();
        if (k0 + 8 < DD) prefetch(k0 + 8);

        // transpose writeout: Xs[256 rows][8 d] -> g_Xt[b][d][m], tf32-rounded
        {
            const int dloc = tid >> 5, lane = tid & 31;
            const int d = k0 + dloc;
            if (d < DD) {
                const int bb = row0 >> 9;
                const int m0g = row0 & 511;
                float* dst = g_Xt + ((long)bb * 304 + d) * 512 + m0g + lane;
#pragma unroll
                for (int i = 0; i < 8; i++)
                    dst[32 * i] = __uint_as_float(tf32r(Xs[(lane + 32 * i) * 9 + dloc]));
            }
        }

#pragma unroll
        for (int k = 0; k < 8; k++) {
            ull ad[8];
#pragma unroll
            for (int i = 0; i < 8; i++) ad[i] = dup2(Xs[(rg * 8 + i) * 9 + k]);
            ull bv[4];
#pragma unroll
            for (int j = 0; j < 4; j++)
                bv[j] = *(const ull*)&Ws[k * 68 + cg * 8 + 2 * j];
#pragma unroll
            for (int i = 0; i < 8; i++)
#pragma unroll
                for (int j = 0; j < 4; j++) fma2(acc[i][j], bv[j], ad[i]);
        }
        __syncthreads();
    }

#pragma unroll
    for (int i = 0; i < 8; i++) {
        const int row = row0 + rg * 8 + i;
#pragma unroll
        for (int j = 0; j < 4; j++) {
            const int c = cg * 8 + 2 * j;
            float lo, hi; unpack2(acc[i][j], lo, hi);
            ull packed = (ull)tf32r(lo) | ((ull)tf32r(hi) << 32);
            if (c < 32) *(ull*)&g_Q[row * AA + c] = packed;
            else        *(ull*)&g_K[row * AA + (c - 32)] = packed;
        }
    }
}

// ---------------------------------------------------------------------------
// Kernel 2: warp-MMA (tf32) fused attention.
// Block = 1 batch x 128 q rows, 256 thr. 8 warps = 4 q-groups x 2 d-halves.
// smem (swizzled 128B rows, XOR (row&7)<<4):
//   Xs @ 0      : Xt chunk [304 d][32 m]        38912 B
//   Ks @ 38912  : K chunk [32 m][32 a, pair-permuted (t,t+4)]   4096 B
//   Qs @ 43008  : Q tile  [128 q][32 a, pair-permuted]         16384 B
//   Aj @ 59392  : adj chunk [128 q][32 m]                      16384 B
// ---------------------------------------------------------------------------
#define SM_XS 0
#define SM_KS 38912
#define SM_QS 43008
#define SM_AJ 59392
#define SM_TOT 75776

__global__ __launch_bounds__(256, 1) void attn_mma_kernel(
    const float* __restrict__ adj,
    float* __restrict__ out)
{
    extern __shared__ char smc[];
    const int tid = threadIdx.x;
    const int lane = tid & 31, w = tid >> 5;
    const int g = lane >> 2, t = lane & 3;     // mma group / thread-in-group
    const int qg = w & 3, dh = w >> 2;
    const int b = blockIdx.x >> 2, row0 = (blockIdx.x & 3) * 128;
    const int qbase = b * NN + row0 + qg * 32;

    // stage Qs once (pair-permuted + swizzled)
    for (int i = tid; i < 4096; i += 256) {
        int r = i >> 5, a = i & 31;
        float v = g_Q[((long)(b * NN + row0 + r)) * AA + a];
        int kt = a >> 3, w8 = a & 7;
        int p = (w8 < 4) ? (2 * w8) : (2 * (w8 - 4) + 1);
        *(float*)(smc + SM_QS + r * 128 + ((((kt * 8 + p) * 4)) ^ ((r & 7) << 4))) = v;
    }

    float4 oacc[2][19];
#pragma unroll
    for (int rt = 0; rt < 2; rt++)
#pragma unroll
        for (int nt = 0; nt < 19; nt++) oacc[rt][nt] = make_float4(0.f, 0.f, 0.f, 0.f);
    float rsum[2][2] = {0.f, 0.f, 0.f, 0.f};

#pragma unroll 1
    for (int c = 0; c < 16; c++) {
        const int m0 = c * 32;
        __syncthreads();   // prior chunk's reads (and Qs staging, iter 0) done

        // ---- stage Ks (pair-permuted) ----
        for (int i = tid; i < 1024; i += 256) {
            int m = i >> 5, a = i & 31;
            float v = g_K[((long)(b * NN + m0 + m)) * AA + a];
            int kt = a >> 3, w8 = a & 7;
            int p = (w8 < 4) ? (2 * w8) : (2 * (w8 - 4) + 1);
            *(float*)(smc + SM_KS + m * 128 + ((((kt * 8 + p) * 4)) ^ ((m & 7) << 4))) = v;
        }
        // ---- stage Xs (Xt chunk, natural m order) ----
        for (int i = tid; i < 2432; i += 256) {
            int d = i >> 3, m4 = i & 7;
            float4 v = *(const float4*)(g_Xt + ((long)b * 304 + d) * 512 + m0 + m4 * 4);
            *(float4*)(smc + SM_XS + d * 128 + ((m4 * 16) ^ ((d & 7) << 4))) = v;
        }
        // ---- stage adj chunk ----
        for (int i = tid; i < 1024; i += 256) {
            int r = i >> 3, m4 = i & 7;
            float4 v = *(const float4*)(adj + ((long)b * NN + row0 + r) * NN + m0 + m4 * 4);
            *(float4*)(smc + SM_AJ + r * 128 + ((m4 * 16) ^ ((r & 7) << 4))) = v;
        }
        __syncthreads();

        // ---- S = Q K^T, then p = exp(s*adj) in registers; P-frags = A-frags ----
        u32 pa[2][4][4];
#pragma unroll
        for (int rt = 0; rt < 2; rt++) {
            const int qrow = qg * 32 + rt * 16;
            u32 qa[4][4];
#pragma unroll
            for (int kt = 0; kt < 4; kt++) {
                int colo = (kt * 32 + 8 * t) ^ (g << 4);
                ull lo = *(const ull*)(smc + SM_QS + (qrow + g) * 128 + colo);
                ull hi = *(const ull*)(smc + SM_QS + (qrow + 8 + g) * 128 + colo);
                qa[kt][0] = (u32)lo; qa[kt][2] = (u32)(lo >> 32);
                qa[kt][1] = (u32)hi; qa[kt][3] = (u32)(hi >> 32);
            }
#pragma unroll
            for (int mnt = 0; mnt < 4; mnt++) {
                float4 s = make_float4(0.f, 0.f, 0.f, 0.f);
#pragma unroll
                for (int kt = 0; kt < 4; kt++) {
                    ull kv = *(const ull*)(smc + SM_KS + (mnt * 8 + g) * 128 +
                                           ((kt * 32 + 8 * t) ^ (g << 4)));
                    mma8(s, qa[kt], (u32)kv, (u32)(kv >> 32));
                }
                const int ac = (mnt * 32 + 8 * t) ^ (g << 4);
                ull a0 = *(const ull*)(smc + SM_AJ + (qrow + g) * 128 + ac);
                ull a1 = *(const ull*)(smc + SM_AJ + (qrow + 8 + g) * 128 + ac);
                float ax, ay, az, aw;
                unpack2(a0, ax, ay);
                unpack2(a1, az, aw);
                u32 p0 = tf32r(__expf(s.x * ax));
                u32 p1 = tf32r(__expf(s.y * ay));
                u32 p2 = tf32r(__expf(s.z * az));
                u32 p3 = tf32r(__expf(s.w * aw));
                rsum[rt][0] += __uint_as_float(p0) + __uint_as_float(p1);
                rsum[rt][1] += __uint_as_float(p2) + __uint_as_float(p3);
                // C-frag (c0,c1,c2,c3) -> A-frag (a0,a1,a2,a3) = (c0,c2,c1,c3)
                pa[rt][mnt][0] = p0; pa[rt][mnt][1] = p2;
                pa[rt][mnt][2] = p1; pa[rt][mnt][3] = p3;
            }
        }

        // ---- O += P @ X^T : B-frags are contiguous m-pairs of Xt ----
#pragma unroll
        for (int nt = 0; nt < 19; nt++) {
            const int dr = dh * 152 + nt * 8 + g;
#pragma unroll
            for (int kt = 0; kt < 4; kt++) {
                ull xv = *(const ull*)(smc + SM_XS + dr * 128 +
                                       ((kt * 32 + 8 * t) ^ (g << 4)));
                mma8(oacc[0][nt], pa[0][kt], (u32)xv, (u32)(xv >> 32));
                mma8(oacc[1][nt], pa[1][kt], (u32)xv, (u32)(xv >> 32));
            }
        }
    }

    // ---- rsum reduce across the t-quad (lanes share g) ----
#pragma unroll
    for (int rt = 0; rt < 2; rt++)
#pragma unroll
        for (int h = 0; h < 2; h++) {
            float v = rsum[rt][h];
            v += __shfl_xor_sync(0xffffffffu, v, 1);
            v += __shfl_xor_sync(0xffffffffu, v, 2);
            rsum[rt][h] = v;
        }

    // ---- normalize + store ----
#pragma unroll
    for (int rt = 0; rt < 2; rt++) {
        const float i0 = 1.0f / rsum[rt][0];
        const float i1 = 1.0f / rsum[rt][1];
        float* r0p = out + ((long)(qbase + rt * 16 + g)) * DD;
        float* r1p = out + ((long)(qbase + rt * 16 + 8 + g)) * DD;
#pragma unroll
        for (int nt = 0; nt < 19; nt++) {
            const int d = dh * 152 + nt * 8 + 2 * t;
            if (d < 299) {   // d even; covers d, d+1 <= 299
                float2 v0 = make_float2(oacc[rt][nt].x * i0, oacc[rt][nt].y * i0);
                float2 v1 = make_float2(oacc[rt][nt].z * i1, oacc[rt][nt].w * i1);
                *(float2*)(r0p + d) = v0;
                *(float2*)(r1p + d) = v1;
            }
        }
    }
}

// ---------------------------------------------------------------------------
extern "C" void kernel_launch(void* const* d_in, const int* in_sizes, int n_in,
                              void* d_out, int out_size)
{
    const float* X   = (const float*)d_in[0];
    const float* adj = (const float*)d_in[1];
    const float* Wq  = (const float*)d_in[2];
    const float* Wk  = (const float*)d_in[3];
    float* out = (float*)d_out;

    cudaFuncSetAttribute(attn_mma_kernel,
                         cudaFuncAttributeMaxDynamicSharedMemorySize, SM_TOT);

    qk_kernel<<<(BB * NN) / 256, 256>>>(X, Wq, Wk);
    attn_mma_kernel<<<BB * 4, 256, SM_TOT>>>(adj, out);
}

// round 8
// speedup vs baseline: 2.4004x; 2.3302x over previous
#include <cuda_runtime.h>

#define BB 128
#define NN 512
#define DD 300
#define AA 32

typedef unsigned long long ull;
typedef unsigned int u32;

// ---------------- helpers ----------------
__device__ __forceinline__ void fma2(ull& d, ull a, ull b) {
    asm("fma.rn.f32x2 %0, %1, %2, %0;" : "+l"(d) : "l"(a), "l"(b));
}
__device__ __forceinline__ ull dup2(float x) {
    ull r; asm("mov.b64 %0, {%1, %1};" : "=l"(r) : "f"(x)); return r;
}
__device__ __forceinline__ void unpack2(ull v, float& lo, float& hi) {
    asm("mov.b64 {%0, %1}, %2;" : "=f"(lo), "=f"(hi) : "l"(v));
}
__device__ __forceinline__ u32 tf32r(float x) {
    u32 r; asm("cvt.rna.tf32.f32 %0, %1;" : "=r"(r) : "f"(x)); return r;
}
__device__ __forceinline__ void mma8(float4& d, const u32* a, u32 b0, u32 b1) {
    asm volatile(
        "mma.sync.aligned.m16n8k8.row.col.f32.tf32.tf32.f32 "
        "{%0,%1,%2,%3}, {%4,%5,%6,%7}, {%8,%9}, {%0,%1,%2,%3};"
        : "+f"(d.x), "+f"(d.y), "+f"(d.z), "+f"(d.w)
        : "r"(a[0]), "r"(a[1]), "r"(a[2]), "r"(a[3]), "r"(b0), "r"(b1));
}
__device__ __forceinline__ u32 smem_u32(const void* p) {
    u32 a; asm("{ .reg .u64 t; cvta.to.shared.u64 t, %1; cvt.u32.u64 %0, t; }"
               : "=r"(a) : "l"(p));
    return a;
}
__device__ __forceinline__ void cp16(u32 dst, const void* src) {
    asm volatile("cp.async.cg.shared.global [%0], [%1], 16;"
                 :: "r"(dst), "l"(src) : "memory");
}
#define CP_COMMIT() asm volatile("cp.async.commit_group;" ::: "memory")
#define CP_WAIT1()  asm volatile("cp.async.wait_group 1;" ::: "memory")
#define CP_WAIT0()  asm volatile("cp.async.wait_group 0;" ::: "memory")

// Scratch: Q,K row-major [B*N, A] (tf32-rounded); Xt = X^T per batch [B][304][512]
__device__ float g_Q[BB * NN * AA];
__device__ float g_K[BB * NN * AA];
__device__ float g_Xt[(long)BB * 304 * 512];   // d rows 300..303 stay zero

// ---------------------------------------------------------------------------
// Kernel 1: Q|K projection (FFMA2) + X transpose writeout, tf32-rounded outs.
// ---------------------------------------------------------------------------
__global__ __launch_bounds__(256) void qk_kernel(
    const float* __restrict__ X,
    const float* __restrict__ Wq,
    const float* __restrict__ Wk)
{
    __shared__ float Xs[256 * 9];
    __shared__ float Ws[8 * 68];

    const int tid = threadIdx.x;
    const int row0 = blockIdx.x * 256;
    const int rg = tid >> 3;
    const int cg = tid & 7;

    ull acc[8][4];
#pragma unroll
    for (int i = 0; i < 8; i++)
#pragma unroll
        for (int j = 0; j < 4; j++) acc[i][j] = 0ull;

    float xf[8], wf[2];
    const float* xrow = X + (long)(row0 + tid) * DD;
    const int wk0 = tid >> 6, wa0 = tid & 63;
    const int wk1 = (tid + 256) >> 6, wa1 = (tid + 256) & 63;

    auto prefetch = [&](int k0) {
        if (k0 + 8 <= DD) {
            float4 v0 = *(const float4*)(xrow + k0);
            float4 v1 = *(const float4*)(xrow + k0 + 4);
            xf[0] = v0.x; xf[1] = v0.y; xf[2] = v0.z; xf[3] = v0.w;
            xf[4] = v1.x; xf[5] = v1.y; xf[6] = v1.z; xf[7] = v1.w;
        } else {
#pragma unroll
            for (int kk = 0; kk < 8; kk++)
                xf[kk] = (k0 + kk < DD) ? xrow[k0 + kk] : 0.0f;
        }
        wf[0] = (k0 + wk0 < DD)
              ? ((wa0 < 32) ? Wq[(k0 + wk0) * AA + wa0] : Wk[(k0 + wk0) * AA + wa0 - 32]) : 0.0f;
        wf[1] = (k0 + wk1 < DD)
              ? ((wa1 < 32) ? Wq[(k0 + wk1) * AA + wa1] : Wk[(k0 + wk1) * AA + wa1 - 32]) : 0.0f;
    };

    prefetch(0);

    for (int k0 = 0; k0 < DD; k0 += 8) {
        {
            float* xs = &Xs[tid * 9];
#pragma unroll
            for (int kk = 0; kk < 8; kk++) xs[kk] = xf[kk];
            Ws[wk0 * 68 + wa0] = wf[0];
            Ws[wk1 * 68 + wa1] = wf[1];
        }
        __syncthreads();
        if (k0 + 8 < DD) prefetch(k0 + 8);

        // transpose writeout: Xs[256 rows][8 d] -> g_Xt[b][d][m], tf32-rounded
        {
            const int dloc = tid >> 5, lane = tid & 31;
            const int d = k0 + dloc;
            if (d < DD) {
                const int bb = row0 >> 9;
                const int m0g = row0 & 511;
                float* dst = g_Xt + ((long)bb * 304 + d) * 512 + m0g + lane;
#pragma unroll
                for (int i = 0; i < 8; i++)
                    dst[32 * i] = __uint_as_float(tf32r(Xs[(lane + 32 * i) * 9 + dloc]));
            }
        }

#pragma unroll
        for (int k = 0; k < 8; k++) {
            ull ad[8];
#pragma unroll
            for (int i = 0; i < 8; i++) ad[i] = dup2(Xs[(rg * 8 + i) * 9 + k]);
            ull bv[4];
#pragma unroll
            for (int j = 0; j < 4; j++)
                bv[j] = *(const ull*)&Ws[k * 68 + cg * 8 + 2 * j];
#pragma unroll
            for (int i = 0; i < 8; i++)
#pragma unroll
                for (int j = 0; j < 4; j++) fma2(acc[i][j], bv[j], ad[i]);
        }
        __syncthreads();
    }

#pragma unroll
    for (int i = 0; i < 8; i++) {
        const int row = row0 + rg * 8 + i;
#pragma unroll
        for (int j = 0; j < 4; j++) {
            const int c = cg * 8 + 2 * j;
            float lo, hi; unpack2(acc[i][j], lo, hi);
            ull packed = (ull)tf32r(lo) | ((ull)tf32r(hi) << 32);
            if (c < 32) *(ull*)&g_Q[row * AA + c] = packed;
            else        *(ull*)&g_K[row * AA + (c - 32)] = packed;
        }
    }
}

// ---------------------------------------------------------------------------
// Kernel 2: warp-MMA (tf32) fused attention, cp.async double-buffered.
// Block = 1 batch x 64 q rows, 256 thr. 8 warps = 4 q-groups(16) x 2 d-halves.
// smem per buffer: Xs [304 d][stride 160B] = 48640 ; Ks [32 m][128B swz] = 4096
// ---------------------------------------------------------------------------
#define XSTRIDE 160
#define KOFF    48640
#define BUFSZ   52736
#define SM_TOT  (2 * BUFSZ)

__global__ __launch_bounds__(256, 1) void attn_mma_kernel(
    const float* __restrict__ adj,
    float* __restrict__ out)
{
    extern __shared__ char smc[];
    const u32 sb = smem_u32(smc);
    const int tid = threadIdx.x;
    const int lane = tid & 31, w = tid >> 5;
    const int g = lane >> 2, t = lane & 3;
    const int qg = w & 3, dh = w >> 2;
    const int b = blockIdx.x >> 3, row0 = (blockIdx.x & 7) * 64;
    const int qbase = b * NN + row0 + qg * 16;   // 16 q rows per group

    // ---- staging lambda (cp.async, one commit per call) ----
    auto stage = [&](int cc, int bi) {
        const int m0 = cc * 32;
        const u32 bx = sb + bi * BUFSZ;
        {   // Ks: 32 rows x 2 x 16B ; 256 cps
            int row = tid >> 3, m4 = tid & 7;
            u32 dst = bx + KOFF + row * 128 + ((m4 * 16) ^ ((row & 7) << 4));
            cp16(dst, g_K + ((long)(b * NN + m0 + row)) * AA + m4 * 4);
        }
#pragma unroll
        for (int tt = 0; tt < 10; tt++) {   // Xs: 304 rows x 8 x 16B = 2432 cps
            int idx = tid + tt * 256;
            if (idx < 2432) {
                int d = idx >> 3, m4 = idx & 7;
                u32 dst = bx + d * XSTRIDE + m4 * 16;
                cp16(dst, g_Xt + ((long)b * 304 + d) * 512 + m0 + m4 * 4);
            }
        }
    };

    // ---- adj fragment prefetch (direct LDG.64, natural layout) ----
    ull ajc0[4], ajc1[4], ajn0[4], ajn1[4];
    const float* ar0 = adj + (long)(qbase + g) * NN + 2 * t;
    const float* ar1 = adj + (long)(qbase + 8 + g) * NN + 2 * t;
    auto adjload = [&](int cc, ull* a0, ull* a1) {
        const int m0 = cc * 32;
#pragma unroll
        for (int mnt = 0; mnt < 4; mnt++) {
            a0[mnt] = *(const ull*)(ar0 + m0 + mnt * 8);
            a1[mnt] = *(const ull*)(ar1 + m0 + mnt * 8);
        }
    };

    // ---- Q fragments: persistent in registers ----
    u32 qa[4][4];
    {
        const float* q0 = g_Q + (long)(qbase + g) * AA;
        const float* q1 = g_Q + (long)(qbase + 8 + g) * AA;
#pragma unroll
        for (int kt = 0; kt < 4; kt++) {
            qa[kt][0] = __float_as_uint(q0[8 * kt + t]);
            qa[kt][1] = __float_as_uint(q1[8 * kt + t]);
            qa[kt][2] = __float_as_uint(q0[8 * kt + t + 4]);
            qa[kt][3] = __float_as_uint(q1[8 * kt + t + 4]);
        }
    }

    stage(0, 0);
    CP_COMMIT();
    adjload(0, ajc0, ajc1);

    float4 oacc[19];
#pragma unroll
    for (int nt = 0; nt < 19; nt++) oacc[nt] = make_float4(0.f, 0.f, 0.f, 0.f);
    float r0s = 0.f, r1s = 0.f;

#pragma unroll 1
    for (int c = 0; c < 16; c++) {
        if (c < 15) {
            stage(c + 1, (c + 1) & 1);
            CP_COMMIT();
            CP_WAIT1();
        } else {
            CP_WAIT0();
        }
        __syncthreads();

        const char* xb = smc + (c & 1) * BUFSZ;
        const char* kb = xb + KOFF;

        // ---- S = Q K^T per mnt, fused exp(s*adj), build A-frags of P ----
        u32 pa[4][4];
#pragma unroll
        for (int mnt = 0; mnt < 4; mnt++) {
            const char* krow = kb + (8 * mnt + g) * 128;
            float4 s = make_float4(0.f, 0.f, 0.f, 0.f);
#pragma unroll
            for (int kt = 0; kt < 4; kt++) {
                u32 b0 = *(const u32*)(krow + (((8 * kt + t) * 4) ^ (g << 4)));
                u32 b1 = *(const u32*)(krow + (((8 * kt + t + 4) * 4) ^ (g << 4)));
                mma8(s, qa[kt], b0, b1);
            }
            float ax, ay, az, aw;
            unpack2(ajc0[mnt], ax, ay);
            unpack2(ajc1[mnt], az, aw);
            u32 p0 = tf32r(__expf(s.x * ax));
            u32 p1 = tf32r(__expf(s.y * ay));
            u32 p2 = tf32r(__expf(s.z * az));
            u32 p3 = tf32r(__expf(s.w * aw));
            r0s += __uint_as_float(p0) + __uint_as_float(p1);
            r1s += __uint_as_float(p2) + __uint_as_float(p3);
            // C-frag (c0,c1,c2,c3) -> A-frag = (c0, c2, c1, c3)
            pa[mnt][0] = p0; pa[mnt][1] = p2; pa[mnt][2] = p1; pa[mnt][3] = p3;
        }

        // prefetch next adj chunk under the AV MMAs
        if (c < 15) adjload(c + 1, ajn0, ajn1);

        // ---- O += P @ X^T ----
#pragma unroll
        for (int nt = 0; nt < 19; nt++) {
            const char* xrow = xb + (dh * 152 + nt * 8 + g) * XSTRIDE;
#pragma unroll
            for (int kt = 0; kt < 4; kt++) {
                ull xv = *(const ull*)(xrow + kt * 32 + 8 * t);
                mma8(oacc[nt], pa[kt], (u32)xv, (u32)(xv >> 32));
            }
        }

#pragma unroll
        for (int mnt = 0; mnt < 4; mnt++) { ajc0[mnt] = ajn0[mnt]; ajc1[mnt] = ajn1[mnt]; }
        __syncthreads();   // all reads of buf (c&1) done before it is restaged
    }

    // ---- rowsum reduce across the t-quad ----
    {
        float v = r0s;
        v += __shfl_xor_sync(0xffffffffu, v, 1);
        v += __shfl_xor_sync(0xffffffffu, v, 2);
        r0s = v;
        v = r1s;
        v += __shfl_xor_sync(0xffffffffu, v, 1);
        v += __shfl_xor_sync(0xffffffffu, v, 2);
        r1s = v;
    }

    // ---- normalize + store ----
    {
        const float i0 = 1.0f / r0s;
        const float i1 = 1.0f / r1s;
        float* r0p = out + (long)(qbase + g) * DD;
        float* r1p = out + (long)(qbase + 8 + g) * DD;
#pragma unroll
        for (int nt = 0; nt < 19; nt++) {
            const int d = dh * 152 + nt * 8 + 2 * t;
            if (d < 299) {
                *(float2*)(r0p + d) = make_float2(oacc[nt].x * i0, oacc[nt].y * i0);
                *(float2*)(r1p + d) = make_float2(oacc[nt].z * i1, oacc[nt].w * i1);
            }
        }
    }
}

// ---------------------------------------------------------------------------
extern "C" void kernel_launch(void* const* d_in, const int* in_sizes, int n_in,
                              void* d_out, int out_size)
{
    const float* X   = (const float*)d_in[0];
    const float* adj = (const float*)d_in[1];
    const float* Wq  = (const float*)d_in[2];
    const float* Wk  = (const float*)d_in[3];
    float* out = (float*)d_out;

    cudaFuncSetAttribute(attn_mma_kernel,
                         cudaFuncAttributeMaxDynamicSharedMemorySize, SM_TOT);

    qk_kernel<<<(BB * NN) / 256, 256>>>(X, Wq, Wk);
    attn_mma_kernel<<<BB * 8, 256, SM_TOT>>>(adj, out);
}